// round 2
// baseline (speedup 1.0000x reference)
#include <cuda_runtime.h>
#include <math.h>

#define TWO_PI_F 6.2831853071795864769f

// ---------------- device scratch ----------------
__device__ float d_h0[64*64*64*64];      // [64,64,64,64]
__device__ float d_h1[64*128*32*32];     // [64,128,32,32]
__device__ float d_Zbuf[64*168*16*16];   // [64,168,16,16]
__device__ float d_g0[64*256*32*32];     // [64,256,32,32]
__device__ float d_g1[64*128*64*64];     // [64,128,64,64]
__device__ float d_a0[64],  d_c0[64];
__device__ float d_a1[128], d_c1[128];
__device__ float d_a2[256], d_c2[256];
__device__ float d_a3[128], d_c3[128];

// ---------------- packed f32x2 helpers ----------------
__device__ __forceinline__ unsigned long long pk2(float lo, float hi){
  unsigned long long r; asm("mov.b64 %0, {%1, %2};" : "=l"(r) : "f"(lo), "f"(hi)); return r;
}
__device__ __forceinline__ void fma2(unsigned long long& d, unsigned long long a, unsigned long long b){
  asm("fma.rn.f32x2 %0, %1, %2, %0;" : "+l"(d) : "l"(a), "l"(b));
}
__device__ __forceinline__ void unpk(unsigned long long v, float& lo, float& hi){
  asm("mov.b64 {%0, %1}, %2;" : "=f"(lo), "=f"(hi) : "l"(v));
}

// =====================================================================
// Strided conv k=4 s=2 p=1. Per thread: 8 ox x CO_T co (packed pairs).
// =====================================================================
template<int IC, int OC, int IH, int IW, int OH, int OW, int OUT_CB,
         int TILE_OY, int CO_BLK, int CI_CHUNK, int NG_OX, int NG_CO,
         bool ACT_IN_LRELU, bool BIAS, bool TANH_OUT>
__global__ void conv_s2_kernel(const float* __restrict__ in, const float* __restrict__ w,
                               const float* __restrict__ bias,
                               const float* __restrict__ a_in, const float* __restrict__ c_in,
                               float* __restrict__ out)
{
  constexpr int NT    = NG_CO * NG_OX * TILE_OY;
  constexpr int CO_T  = CO_BLK / NG_CO;
  constexpr int CO_P  = CO_T / 2;
  constexpr int ROWS  = 2*TILE_OY + 2;
  constexpr int COLSP = IW + 4;
  static_assert(OW / NG_OX == 8, "");

  __shared__ __align__(16) float sIn[CI_CHUNK][ROWS][COLSP];
  __shared__ __align__(16) float sW [CI_CHUNK][16][CO_BLK];

  const int tid   = threadIdx.x;
  const int co_g  = tid % NG_CO;
  const int ox_g  = (tid / NG_CO) % NG_OX;
  const int oy_l  = tid / (NG_CO * NG_OX);
  const int co_base = blockIdx.y * CO_BLK;
  const int b     = blockIdx.z;
  const int oy0   = blockIdx.x * TILE_OY;
  const int iy0   = 2*oy0 - 1;
  const int ox0   = ox_g * 8;
  const int co_t0 = co_g * CO_T;

  unsigned long long acc[8][CO_P];
  #pragma unroll
  for (int u=0;u<8;u++)
    #pragma unroll
    for (int j=0;j<CO_P;j++) acc[u][j] = 0ULL;

  for (int ci0 = 0; ci0 < IC; ci0 += CI_CHUNK) {
    for (int idx = tid; idx < CI_CHUNK*ROWS*COLSP; idx += NT) {
      int cc  = idx / (ROWS*COLSP);
      int rem = idx % (ROWS*COLSP);
      int r   = rem / COLSP, col = rem % COLSP;
      int iy  = iy0 + r, ix = col - 1;
      float v = 0.f;
      if (ix >= 0 && ix < IW && iy >= 0 && iy < IH) {
        v = in[((b*IC + ci0+cc)*IH + iy)*IW + ix];
        if constexpr (ACT_IN_LRELU) {
          float t = fmaf(a_in[ci0+cc], v, c_in[ci0+cc]);
          v = t > 0.f ? t : 0.2f*t;
        }
      }
      sIn[cc][r][col] = v;
    }
    for (int idx = tid; idx < CI_CHUNK*16*CO_BLK; idx += NT) {
      int cc  = idx / (16*CO_BLK);
      int rem = idx % (16*CO_BLK);
      int k   = rem / CO_BLK, co = rem % CO_BLK;
      sW[cc][k][co] = w[((co_base+co)*IC + ci0+cc)*16 + k];
    }
    __syncthreads();

    #pragma unroll
    for (int cc=0; cc<CI_CHUNK; cc++) {
      #pragma unroll
      for (int k=0;k<16;k++) {
        const int ky = k >> 2, kx = k & 3;
        unsigned long long wv[CO_P];
        #pragma unroll
        for (int j=0;j<CO_P;j++)
          wv[j] = *reinterpret_cast<const unsigned long long*>(&sW[cc][k][co_t0 + 2*j]);
        const float* rowp = &sIn[cc][2*oy_l + ky][0];
        #pragma unroll
        for (int u=0;u<8;u++) {
          float iv = rowp[2*(ox0+u) + kx];
          unsigned long long pv = pk2(iv, iv);
          #pragma unroll
          for (int j=0;j<CO_P;j++) fma2(acc[u][j], pv, wv[j]);
        }
      }
    }
    __syncthreads();
  }

  const int oy = oy0 + oy_l;
  #pragma unroll
  for (int j=0;j<CO_P;j++){
    float v0[8], v1[8];
    #pragma unroll
    for (int u=0;u<8;u++) unpk(acc[u][j], v0[u], v1[u]);
    const int co = co_base + co_t0 + 2*j;
    if constexpr (BIAS) {
      float b0 = bias[co], b1 = bias[co+1];
      #pragma unroll
      for (int u=0;u<8;u++){ v0[u]+=b0; v1[u]+=b1; }
    }
    if constexpr (TANH_OUT) {
      #pragma unroll
      for (int u=0;u<8;u++){ v0[u]=tanhf(v0[u]); v1[u]=tanhf(v1[u]); }
    }
    float4* p0 = reinterpret_cast<float4*>(&out[((b*OUT_CB + co  )*OH + oy)*OW + ox0]);
    float4* p1 = reinterpret_cast<float4*>(&out[((b*OUT_CB + co+1)*OH + oy)*OW + ox0]);
    p0[0] = make_float4(v0[0],v0[1],v0[2],v0[3]);
    p0[1] = make_float4(v0[4],v0[5],v0[6],v0[7]);
    p1[0] = make_float4(v1[0],v1[1],v1[2],v1[3]);
    p1[1] = make_float4(v1[4],v1[5],v1[6],v1[7]);
  }
}

// =====================================================================
// Transposed conv k=4 s=2 p=1 via parity decomposition:
// out[b,co,2m+ry,2n+rx] = sum_ci sum_{d,e} act(in[b,ci,m+d+ry-1,n+e+rx-1])
//                         * w[ci,co,3-ry-2d,3-rx-2e]
// =====================================================================
template<int IC, int OC, int IH, int IW, int OUT_CB,
         int TILE_M, int CO_BLK, int CI_CHUNK, int NG_N, int NG_CO,
         bool ACT_IN_RELU>
__global__ void deconv_kernel(const float* __restrict__ in, const float* __restrict__ w,
                              const float* __restrict__ a_in, const float* __restrict__ c_in,
                              float* __restrict__ out)
{
  constexpr int NT    = NG_N * NG_CO * TILE_M;
  constexpr int CO_T  = CO_BLK / NG_CO;
  constexpr int CO_P  = CO_T / 2;
  constexpr int ROWS  = TILE_M + 1;
  constexpr int COLSP = IW + 2;
  constexpr int NCO_G = OC / CO_BLK;
  static_assert(IW / NG_N == 8, "");

  __shared__ __align__(16) float sIn[CI_CHUNK][ROWS][COLSP];
  __shared__ __align__(16) float sW [CI_CHUNK][4][CO_BLK];

  const int tid    = threadIdx.x;
  const int n_g    = tid % NG_N;
  const int co_g   = (tid / NG_N) % NG_CO;
  const int m_l    = tid / (NG_N * NG_CO);
  const int co_grp = blockIdx.x % NCO_G;
  const int m_tile = blockIdx.x / NCO_G;
  const int ry     = blockIdx.y >> 1, rx = blockIdx.y & 1;
  const int b      = blockIdx.z;
  const int m0     = m_tile * TILE_M;
  const int co_base= co_grp * CO_BLK;
  const int n0     = n_g * 8;
  const int co_t0  = co_g * CO_T;

  unsigned long long acc[8][CO_P];
  #pragma unroll
  for (int u=0;u<8;u++)
    #pragma unroll
    for (int j=0;j<CO_P;j++) acc[u][j] = 0ULL;

  for (int ci0 = 0; ci0 < IC; ci0 += CI_CHUNK) {
    for (int idx = tid; idx < CI_CHUNK*ROWS*COLSP; idx += NT) {
      int cc  = idx / (ROWS*COLSP);
      int rem = idx % (ROWS*COLSP);
      int r   = rem / COLSP, col = rem % COLSP;
      int gy  = m0 + ry - 1 + r;
      int gx  = rx - 1 + col;
      float v = 0.f;
      if (gy >= 0 && gy < IH && gx >= 0 && gx < IW) {
        v = in[((b*IC + ci0+cc)*IH + gy)*IW + gx];
        if constexpr (ACT_IN_RELU)
          v = fmaxf(fmaf(a_in[ci0+cc], v, c_in[ci0+cc]), 0.f);
      }
      sIn[cc][r][col] = v;
    }
    for (int idx = tid; idx < CI_CHUNK*4*CO_BLK; idx += NT) {
      int cc  = idx / (4*CO_BLK);
      int rem = idx % (4*CO_BLK);
      int t4  = rem / CO_BLK, co = rem % CO_BLK;
      int dd = t4 >> 1, ee = t4 & 1;
      sW[cc][t4][co] = w[((ci0+cc)*OC + co_base+co)*16 + (3-ry-2*dd)*4 + (3-rx-2*ee)];
    }
    __syncthreads();

    #pragma unroll
    for (int cc=0; cc<CI_CHUNK; cc++) {
      #pragma unroll
      for (int t4=0;t4<4;t4++) {
        const int dd = t4 >> 1, ee = t4 & 1;
        unsigned long long wv[CO_P];
        #pragma unroll
        for (int j=0;j<CO_P;j++)
          wv[j] = *reinterpret_cast<const unsigned long long*>(&sW[cc][t4][co_t0 + 2*j]);
        const float* rowp = &sIn[cc][m_l + dd][0];
        #pragma unroll
        for (int u=0;u<8;u++) {
          float iv = rowp[n0 + u + ee];
          unsigned long long pv = pk2(iv, iv);
          #pragma unroll
          for (int j=0;j<CO_P;j++) fma2(acc[u][j], pv, wv[j]);
        }
      }
    }
    __syncthreads();
  }

  const int oy = 2*(m0 + m_l) + ry;
  const int OW2 = 2*IW, OH2 = 2*IH;
  #pragma unroll
  for (int j=0;j<CO_P;j++){
    const int co = co_base + co_t0 + 2*j;
    float* r0 = &out[((b*OUT_CB + co  )*OH2 + oy)*OW2 + rx];
    float* r1 = &out[((b*OUT_CB + co+1)*OH2 + oy)*OW2 + rx];
    #pragma unroll
    for (int u=0;u<8;u++){
      float v0, v1; unpk(acc[u][j], v0, v1);
      r0[2*(n0+u)] = v0;
      r1[2*(n0+u)] = v1;
    }
  }
}

// =====================================================================
// Final deconv 128->3 with bias + tanh
// =====================================================================
__global__ void deconv2_kernel(const float* __restrict__ in, const float* __restrict__ w,
                               const float* __restrict__ bias,
                               const float* __restrict__ a_in, const float* __restrict__ c_in,
                               float* __restrict__ out)
{
  constexpr int IC=128, OC=3, IH=64, IW=64, TILE_M=16, CI=4, NG_N=8;
  constexpr int NT=128, ROWS=TILE_M+1, COLSP=IW+2;
  __shared__ float sIn[CI][ROWS][COLSP];
  __shared__ float sW[CI][4][4];

  const int tid = threadIdx.x;
  const int n_g = tid % NG_N;
  const int m_l = tid / NG_N;
  const int m0  = blockIdx.x * TILE_M;
  const int ry  = blockIdx.y >> 1, rx = blockIdx.y & 1;
  const int b   = blockIdx.z;
  const int n0  = n_g * 8;

  float acc[3][8];
  #pragma unroll
  for (int co=0;co<3;co++)
    #pragma unroll
    for (int u=0;u<8;u++) acc[co][u] = 0.f;

  for (int ci0 = 0; ci0 < IC; ci0 += CI) {
    for (int idx = tid; idx < CI*ROWS*COLSP; idx += NT) {
      int cc  = idx / (ROWS*COLSP);
      int rem = idx % (ROWS*COLSP);
      int r   = rem / COLSP, col = rem % COLSP;
      int gy  = m0 + ry - 1 + r;
      int gx  = rx - 1 + col;
      float v = 0.f;
      if (gy >= 0 && gy < IH && gx >= 0 && gx < IW)
        v = fmaxf(fmaf(a_in[ci0+cc], in[((b*IC + ci0+cc)*IH + gy)*IW + gx], c_in[ci0+cc]), 0.f);
      sIn[cc][r][col] = v;
    }
    if (tid < 48) {
      int cc = tid / 12, t4 = (tid / 3) % 4, co = tid % 3;
      int dd = t4 >> 1, ee = t4 & 1;
      sW[cc][t4][co] = w[((ci0+cc)*OC + co)*16 + (3-ry-2*dd)*4 + (3-rx-2*ee)];
    }
    __syncthreads();

    #pragma unroll
    for (int cc=0; cc<CI; cc++) {
      #pragma unroll
      for (int t4=0;t4<4;t4++) {
        const int dd = t4 >> 1, ee = t4 & 1;
        float w0 = sW[cc][t4][0], w1 = sW[cc][t4][1], w2 = sW[cc][t4][2];
        const float* rowp = &sIn[cc][m_l + dd][0];
        #pragma unroll
        for (int u=0;u<8;u++) {
          float iv = rowp[n0 + u + ee];
          acc[0][u] = fmaf(iv, w0, acc[0][u]);
          acc[1][u] = fmaf(iv, w1, acc[1][u]);
          acc[2][u] = fmaf(iv, w2, acc[2][u]);
        }
      }
    }
    __syncthreads();
  }

  const int oy = 2*(m0 + m_l) + ry;
  #pragma unroll
  for (int co=0;co<3;co++){
    float bb = bias[co];
    float* rp = &out[((b*3 + co)*128 + oy)*128 + rx];
    #pragma unroll
    for (int u=0;u<8;u++)
      rp[2*(n0+u)] = tanhf(acc[co][u] + bb);
  }
}

// =====================================================================
// Per-channel BN stats -> a = g*rsqrt(var+eps), c = be - mean*a
// =====================================================================
template<int C, int HW>
__global__ void stats_kernel(const float* __restrict__ in, const float* __restrict__ g,
                             const float* __restrict__ be,
                             float* __restrict__ a, float* __restrict__ cv)
{
  const int c = blockIdx.x;
  const int tid = threadIdx.x;  // 256
  double s = 0.0, s2 = 0.0;
  for (int b = 0; b < 64; b++) {
    const float* p = in + ((size_t)(b*C + c))*HW;
    for (int i = tid; i < HW; i += 256) { float v = p[i]; s += v; s2 += (double)v*v; }
  }
  __shared__ double sh[2][256];
  sh[0][tid] = s; sh[1][tid] = s2; __syncthreads();
  for (int off = 128; off > 0; off >>= 1) {
    if (tid < off) { sh[0][tid] += sh[0][tid+off]; sh[1][tid] += sh[1][tid+off]; }
    __syncthreads();
  }
  if (tid == 0) {
    double N = 64.0 * HW;
    double mean = sh[0][0] / N;
    double var  = sh[1][0] / N - mean*mean;
    float rs = (float)(1.0 / sqrt(var + 1e-5));
    float av = g[c] * rs;
    a[c] = av;
    cv[c] = be[c] - (float)mean * av;
  }
}

// =====================================================================
// Pack Z_l (ch 64..95) and Z_g (ch 96..159) into Zbuf
// =====================================================================
__global__ void pack_kernel(const float* __restrict__ Zl, const float* __restrict__ Zg,
                            float* __restrict__ Zbuf)
{
  int idx = blockIdx.x * 256 + threadIdx.x;
  const int nl = 64*32*256;
  if (idx < nl) {
    int b = idx / (32*256); int r = idx % (32*256);
    Zbuf[(b*168 + 64)*256 + r] = Zl[idx];
  }
  const int ng = 64*64*256;
  if (idx < ng) {
    int b = idx / (64*256); int r = idx % (64*256);
    Zbuf[(b*168 + 96)*256 + r] = Zg[idx];
  }
}

// =====================================================================
// Wave latent: zg -> relu FC -> K1,K2 -> Z_p (ch 160..167)
// =====================================================================
__global__ void wave_kernel(const float* __restrict__ Zg, const float* __restrict__ phi,
                            const float* __restrict__ lW, const float* __restrict__ lb,
                            const float* __restrict__ l1W, const float* __restrict__ l1b,
                            const float* __restrict__ l2W, const float* __restrict__ l2b,
                            float* __restrict__ Zbuf)
{
  const int b = blockIdx.x;
  const int t = threadIdx.x;  // 64
  __shared__ float zg[64], x[64], K[16];
  zg[t] = Zg[(b*64 + t)*256];
  __syncthreads();
  float acc = lb[t];
  #pragma unroll 8
  for (int g = 0; g < 64; g++) acc = fmaf(zg[g], lW[t*64+g], acc);
  x[t] = fmaxf(acc, 0.f);
  __syncthreads();
  if (t < 16) {
    int p = t & 7;
    const float* W  = (t < 8) ? l1W : l2W;
    const float* bb = (t < 8) ? l1b : l2b;
    float k = bb[p];
    #pragma unroll 8
    for (int h = 0; h < 64; h++) k = fmaf(x[h], W[p*64+h], k);
    K[t] = k;
  }
  __syncthreads();
  for (int idx = t; idx < 8*256; idx += 64) {
    int p = idx >> 8; int ij = idx & 255; int i = ij >> 4; int j = ij & 15;
    float wv = K[p]*(float)i + K[p+8]*(float)j + phi[b*8+p]*TWO_PI_F;
    Zbuf[(b*168 + 160 + p)*256 + ij] = sinf(wv);
  }
}

// =====================================================================
extern "C" void kernel_launch(void* const* d_in, const int* in_sizes, int n_in,
                              void* d_out, int out_size)
{
  const float* Zl   = (const float*)d_in[0];
  const float* Zg   = (const float*)d_in[1];
  const float* imgs = (const float*)d_in[2];
  const float* phi  = (const float*)d_in[3];
  const float* lW   = (const float*)d_in[4];
  const float* lb   = (const float*)d_in[5];
  const float* l1W  = (const float*)d_in[6];
  const float* l1b  = (const float*)d_in[7];
  const float* l2W  = (const float*)d_in[8];
  const float* l2b  = (const float*)d_in[9];
  const float* cw0  = (const float*)d_in[10];
  const float* cg0  = (const float*)d_in[12];
  const float* cbe0 = (const float*)d_in[13];
  const float* cw1  = (const float*)d_in[14];
  const float* cg1  = (const float*)d_in[16];
  const float* cbe1 = (const float*)d_in[17];
  const float* cw2  = (const float*)d_in[18];
  const float* cb2  = (const float*)d_in[19];
  const float* gw0  = (const float*)d_in[20];
  const float* gg0  = (const float*)d_in[22];
  const float* gbe0 = (const float*)d_in[23];
  const float* gw1  = (const float*)d_in[24];
  const float* gg1  = (const float*)d_in[26];
  const float* gbe1 = (const float*)d_in[27];
  const float* gw2  = (const float*)d_in[28];
  const float* gb2  = (const float*)d_in[29];
  float* out = (float*)d_out;

  float *h0,*h1,*Zb,*g0,*g1,*a0,*c0,*a1,*c1,*a2,*c2,*a3,*c3;
  cudaGetSymbolAddress((void**)&h0, d_h0);
  cudaGetSymbolAddress((void**)&h1, d_h1);
  cudaGetSymbolAddress((void**)&Zb, d_Zbuf);
  cudaGetSymbolAddress((void**)&g0, d_g0);
  cudaGetSymbolAddress((void**)&g1, d_g1);
  cudaGetSymbolAddress((void**)&a0, d_a0); cudaGetSymbolAddress((void**)&c0, d_c0);
  cudaGetSymbolAddress((void**)&a1, d_a1); cudaGetSymbolAddress((void**)&c1, d_c1);
  cudaGetSymbolAddress((void**)&a2, d_a2); cudaGetSymbolAddress((void**)&c2, d_c2);
  cudaGetSymbolAddress((void**)&a3, d_a3); cudaGetSymbolAddress((void**)&c3, d_c3);

  // encoder
  conv_s2_kernel<3,64,128,128,64,64, 64, 4,64,3,8,8, false,false,false>
      <<<dim3(16,1,64),256>>>(imgs, cw0, nullptr, nullptr, nullptr, h0);
  stats_kernel<64,4096><<<64,256>>>(h0, cg0, cbe0, a0, c0);
  conv_s2_kernel<64,128,64,64,32,32, 128, 8,64,4,4,8, true,false,false>
      <<<dim3(4,2,64),256>>>(h0, cw1, nullptr, a0, c0, h1);
  stats_kernel<128,1024><<<128,256>>>(h1, cg1, cbe1, a1, c1);
  conv_s2_kernel<128,64,32,32,16,16, 168, 8,64,4,2,16, true,true,true>
      <<<dim3(2,1,64),256>>>(h1, cw2, cb2, a1, c1, Zb);

  // latent assembly
  pack_kernel<<<4096,256>>>(Zl, Zg, Zb);
  wave_kernel<<<64,64>>>(Zg, phi, lW, lb, l1W, l1b, l2W, l2b, Zb);

  // generator
  deconv_kernel<168,256,16,16, 256, 8,128,8,2,16, false>
      <<<dim3(4,4,64),256>>>(Zb, gw0, nullptr, nullptr, g0);
  stats_kernel<256,1024><<<256,256>>>(g0, gg0, gbe0, a2, c2);
  deconv_kernel<256,128,32,32, 128, 8,128,8,4,16, true>
      <<<dim3(4,4,64),512>>>(g0, gw1, a2, c2, g1);
  stats_kernel<128,4096><<<128,256>>>(g1, gg1, gbe1, a3, c3);
  deconv2_kernel<<<dim3(4,4,64),128>>>(g1, gw2, gb2, a3, c3, out);
}

// round 3
// speedup vs baseline: 1.8471x; 1.8471x over previous
#include <cuda_runtime.h>
#include <math.h>

#define TWO_PI_F 6.2831853071795864769f

// ---------------- device scratch ----------------
__device__ float d_h0[64*64*64*64];      // [64,64,64,64]
__device__ float d_h1[64*128*32*32];     // [64,128,32,32]
__device__ float d_Zbuf[64*168*16*16];   // [64,168,16,16]
__device__ float d_g0[64*256*32*32];     // [64,256,32,32]
__device__ float d_g1[64*128*64*64];     // [64,128,64,64]
__device__ float d_stat0[128];           // [sum64 | sq64]
__device__ float d_stat1[256];           // [sum128 | sq128]
__device__ float d_stat2[512];           // [sum256 | sq256]
__device__ float d_stat3[256];           // [sum128 | sq128]
__device__ float d_a0[64],  d_c0[64];
__device__ float d_a1[128], d_c1[128];
__device__ float d_a2[256], d_c2[256];
__device__ float d_a3[128], d_c3[128];

// ---------------- packed f32x2 helpers ----------------
__device__ __forceinline__ unsigned long long pk2(float lo, float hi){
  unsigned long long r; asm("mov.b64 %0, {%1, %2};" : "=l"(r) : "f"(lo), "f"(hi)); return r;
}
__device__ __forceinline__ void fma2(unsigned long long& d, unsigned long long a, unsigned long long b){
  asm("fma.rn.f32x2 %0, %1, %2, %0;" : "+l"(d) : "l"(a), "l"(b));
}
__device__ __forceinline__ void unpk(unsigned long long v, float& lo, float& hi){
  asm("mov.b64 {%0, %1}, %2;" : "=f"(lo), "=f"(hi) : "l"(v));
}

// =====================================================================
// Strided conv k=4 s=2 p=1. Per thread: 8 ox x CO_T co (packed pairs).
// Optional fused BN-stats reduction into global stat buffer [sum OC | sq OC].
// =====================================================================
template<int IC, int OC, int IH, int IW, int OH, int OW, int OUT_CB,
         int TILE_OY, int CO_BLK, int CI_CHUNK, int NG_OX, int NG_CO,
         bool ACT_IN_LRELU, bool BIAS, bool TANH_OUT, bool REDUCE>
__global__ void __launch_bounds__(NG_CO*NG_OX*TILE_OY)
conv_s2_kernel(const float* __restrict__ in, const float* __restrict__ w,
               const float* __restrict__ bias,
               const float* __restrict__ a_in, const float* __restrict__ c_in,
               float* __restrict__ out, float* __restrict__ stat)
{
  constexpr int NT    = NG_CO * NG_OX * TILE_OY;
  constexpr int CO_T  = CO_BLK / NG_CO;
  constexpr int CO_P  = CO_T / 2;
  constexpr int ROWS  = 2*TILE_OY + 2;
  constexpr int COLSP = IW + 4;
  static_assert(OW / NG_OX == 8, "");

  __shared__ __align__(16) float sIn[CI_CHUNK][ROWS][COLSP];
  __shared__ __align__(16) float sW [CI_CHUNK][16][CO_BLK];
  __shared__ float sRed[2*CO_BLK];

  const int tid   = threadIdx.x;
  const int co_g  = tid % NG_CO;
  const int ox_g  = (tid / NG_CO) % NG_OX;
  const int oy_l  = tid / (NG_CO * NG_OX);
  const int co_base = blockIdx.y * CO_BLK;
  const int b     = blockIdx.z;
  const int oy0   = blockIdx.x * TILE_OY;
  const int iy0   = 2*oy0 - 1;
  const int ox0   = ox_g * 8;
  const int co_t0 = co_g * CO_T;

  unsigned long long acc[8][CO_P];
  #pragma unroll
  for (int u=0;u<8;u++)
    #pragma unroll
    for (int j=0;j<CO_P;j++) acc[u][j] = 0ULL;

  for (int ci0 = 0; ci0 < IC; ci0 += CI_CHUNK) {
    for (int idx = tid; idx < CI_CHUNK*ROWS*COLSP; idx += NT) {
      int cc  = idx / (ROWS*COLSP);
      int rem = idx % (ROWS*COLSP);
      int r   = rem / COLSP, col = rem % COLSP;
      int iy  = iy0 + r, ix = col - 1;
      float v = 0.f;
      if (ix >= 0 && ix < IW && iy >= 0 && iy < IH) {
        v = in[((b*IC + ci0+cc)*IH + iy)*IW + ix];
        if constexpr (ACT_IN_LRELU) {
          float t = fmaf(a_in[ci0+cc], v, c_in[ci0+cc]);
          v = t > 0.f ? t : 0.2f*t;
        }
      }
      sIn[cc][r][col] = v;
    }
    for (int idx = tid; idx < CI_CHUNK*16*CO_BLK; idx += NT) {
      int cc  = idx / (16*CO_BLK);
      int rem = idx % (16*CO_BLK);
      int k   = rem / CO_BLK, co = rem % CO_BLK;
      sW[cc][k][co] = w[((co_base+co)*IC + ci0+cc)*16 + k];
    }
    __syncthreads();

    #pragma unroll
    for (int cc=0; cc<CI_CHUNK; cc++) {
      #pragma unroll
      for (int k=0;k<16;k++) {
        const int ky = k >> 2, kx = k & 3;
        unsigned long long wv[CO_P];
        #pragma unroll
        for (int j=0;j<CO_P;j++)
          wv[j] = *reinterpret_cast<const unsigned long long*>(&sW[cc][k][co_t0 + 2*j]);
        const float* rowp = &sIn[cc][2*oy_l + ky][0];
        #pragma unroll
        for (int u=0;u<8;u++) {
          float iv = rowp[2*(ox0+u) + kx];
          unsigned long long pv = pk2(iv, iv);
          #pragma unroll
          for (int j=0;j<CO_P;j++) fma2(acc[u][j], pv, wv[j]);
        }
      }
    }
    __syncthreads();
  }

  if constexpr (REDUCE) {
    for (int i = tid; i < 2*CO_BLK; i += NT) sRed[i] = 0.f;
    __syncthreads();
  }

  const int oy = oy0 + oy_l;
  #pragma unroll
  for (int j=0;j<CO_P;j++){
    float v0[8], v1[8];
    #pragma unroll
    for (int u=0;u<8;u++) unpk(acc[u][j], v0[u], v1[u]);
    const int co = co_base + co_t0 + 2*j;
    if constexpr (BIAS) {
      float b0 = bias[co], b1 = bias[co+1];
      #pragma unroll
      for (int u=0;u<8;u++){ v0[u]+=b0; v1[u]+=b1; }
    }
    if constexpr (TANH_OUT) {
      #pragma unroll
      for (int u=0;u<8;u++){ v0[u]=tanhf(v0[u]); v1[u]=tanhf(v1[u]); }
    }
    float4* p0 = reinterpret_cast<float4*>(&out[((b*OUT_CB + co  )*OH + oy)*OW + ox0]);
    float4* p1 = reinterpret_cast<float4*>(&out[((b*OUT_CB + co+1)*OH + oy)*OW + ox0]);
    p0[0] = make_float4(v0[0],v0[1],v0[2],v0[3]);
    p0[1] = make_float4(v0[4],v0[5],v0[6],v0[7]);
    p1[0] = make_float4(v1[0],v1[1],v1[2],v1[3]);
    p1[1] = make_float4(v1[4],v1[5],v1[6],v1[7]);
    if constexpr (REDUCE) {
      float s0=0.f,q0=0.f,s1=0.f,q1=0.f;
      #pragma unroll
      for (int u=0;u<8;u++){ s0+=v0[u]; q0=fmaf(v0[u],v0[u],q0); s1+=v1[u]; q1=fmaf(v1[u],v1[u],q1); }
      int cl = co_t0 + 2*j;
      atomicAdd(&sRed[cl],            s0);
      atomicAdd(&sRed[CO_BLK+cl],     q0);
      atomicAdd(&sRed[cl+1],          s1);
      atomicAdd(&sRed[CO_BLK+cl+1],   q1);
    }
  }
  if constexpr (REDUCE) {
    __syncthreads();
    if (tid < 2*CO_BLK) {
      int cl = (tid < CO_BLK) ? tid : (tid - CO_BLK);
      int off = (tid < CO_BLK) ? 0 : OC;
      atomicAdd(&stat[off + co_base + cl], sRed[tid]);
    }
  }
}

// =====================================================================
// Transposed conv k=4 s=2 p=1 via parity decomposition:
// out[b,co,2m+ry,2n+rx] = sum_ci sum_{d,e} act(in[b,ci,m+d+ry-1,n+e+rx-1])
//                         * w[ci,co,3-ry-2d,3-rx-2e]
// =====================================================================
template<int IC, int OC, int IH, int IW, int OUT_CB,
         int TILE_M, int CO_BLK, int CI_CHUNK, int NG_N, int NG_CO,
         bool ACT_IN_RELU, bool REDUCE>
__global__ void __launch_bounds__(NG_N*NG_CO*TILE_M)
deconv_kernel(const float* __restrict__ in, const float* __restrict__ w,
              const float* __restrict__ a_in, const float* __restrict__ c_in,
              float* __restrict__ out, float* __restrict__ stat)
{
  constexpr int NT    = NG_N * NG_CO * TILE_M;
  constexpr int CO_T  = CO_BLK / NG_CO;
  constexpr int CO_P  = CO_T / 2;
  constexpr int ROWS  = TILE_M + 1;
  constexpr int COLSP = IW + 2;
  constexpr int NCO_G = OC / CO_BLK;
  static_assert(IW / NG_N == 8, "");

  __shared__ __align__(16) float sIn[CI_CHUNK][ROWS][COLSP];
  __shared__ __align__(16) float sW [CI_CHUNK][4][CO_BLK];
  __shared__ float sRed[2*CO_BLK];

  const int tid    = threadIdx.x;
  const int n_g    = tid % NG_N;
  const int co_g   = (tid / NG_N) % NG_CO;
  const int m_l    = tid / (NG_N * NG_CO);
  const int co_grp = blockIdx.x % NCO_G;
  const int m_tile = blockIdx.x / NCO_G;
  const int ry     = blockIdx.y >> 1, rx = blockIdx.y & 1;
  const int b      = blockIdx.z;
  const int m0     = m_tile * TILE_M;
  const int co_base= co_grp * CO_BLK;
  const int n0     = n_g * 8;
  const int co_t0  = co_g * CO_T;

  unsigned long long acc[8][CO_P];
  #pragma unroll
  for (int u=0;u<8;u++)
    #pragma unroll
    for (int j=0;j<CO_P;j++) acc[u][j] = 0ULL;

  for (int ci0 = 0; ci0 < IC; ci0 += CI_CHUNK) {
    for (int idx = tid; idx < CI_CHUNK*ROWS*COLSP; idx += NT) {
      int cc  = idx / (ROWS*COLSP);
      int rem = idx % (ROWS*COLSP);
      int r   = rem / COLSP, col = rem % COLSP;
      int gy  = m0 + ry - 1 + r;
      int gx  = rx - 1 + col;
      float v = 0.f;
      if (gy >= 0 && gy < IH && gx >= 0 && gx < IW) {
        v = in[((b*IC + ci0+cc)*IH + gy)*IW + gx];
        if constexpr (ACT_IN_RELU)
          v = fmaxf(fmaf(a_in[ci0+cc], v, c_in[ci0+cc]), 0.f);
      }
      sIn[cc][r][col] = v;
    }
    for (int idx = tid; idx < CI_CHUNK*4*CO_BLK; idx += NT) {
      int cc  = idx / (4*CO_BLK);
      int rem = idx % (4*CO_BLK);
      int t4  = rem / CO_BLK, co = rem % CO_BLK;
      int dd = t4 >> 1, ee = t4 & 1;
      sW[cc][t4][co] = w[((ci0+cc)*OC + co_base+co)*16 + (3-ry-2*dd)*4 + (3-rx-2*ee)];
    }
    __syncthreads();

    #pragma unroll
    for (int cc=0; cc<CI_CHUNK; cc++) {
      #pragma unroll
      for (int t4=0;t4<4;t4++) {
        const int dd = t4 >> 1, ee = t4 & 1;
        unsigned long long wv[CO_P];
        #pragma unroll
        for (int j=0;j<CO_P;j++)
          wv[j] = *reinterpret_cast<const unsigned long long*>(&sW[cc][t4][co_t0 + 2*j]);
        const float* rowp = &sIn[cc][m_l + dd][0];
        #pragma unroll
        for (int u=0;u<8;u++) {
          float iv = rowp[n0 + u + ee];
          unsigned long long pv = pk2(iv, iv);
          #pragma unroll
          for (int j=0;j<CO_P;j++) fma2(acc[u][j], pv, wv[j]);
        }
      }
    }
    __syncthreads();
  }

  if constexpr (REDUCE) {
    for (int i = tid; i < 2*CO_BLK; i += NT) sRed[i] = 0.f;
    __syncthreads();
  }

  const int oy = 2*(m0 + m_l) + ry;
  const int OW2 = 2*IW, OH2 = 2*IH;
  #pragma unroll
  for (int j=0;j<CO_P;j++){
    const int co = co_base + co_t0 + 2*j;
    float* r0 = &out[((b*OUT_CB + co  )*OH2 + oy)*OW2 + rx];
    float* r1 = &out[((b*OUT_CB + co+1)*OH2 + oy)*OW2 + rx];
    float s0=0.f,q0=0.f,s1=0.f,q1=0.f;
    #pragma unroll
    for (int u=0;u<8;u++){
      float v0, v1; unpk(acc[u][j], v0, v1);
      r0[2*(n0+u)] = v0;
      r1[2*(n0+u)] = v1;
      if constexpr (REDUCE) { s0+=v0; q0=fmaf(v0,v0,q0); s1+=v1; q1=fmaf(v1,v1,q1); }
    }
    if constexpr (REDUCE) {
      int cl = co_t0 + 2*j;
      atomicAdd(&sRed[cl],          s0);
      atomicAdd(&sRed[CO_BLK+cl],   q0);
      atomicAdd(&sRed[cl+1],        s1);
      atomicAdd(&sRed[CO_BLK+cl+1], q1);
    }
  }
  if constexpr (REDUCE) {
    __syncthreads();
    if (tid < 2*CO_BLK) {
      int cl = (tid < CO_BLK) ? tid : (tid - CO_BLK);
      int off = (tid < CO_BLK) ? 0 : OC;
      atomicAdd(&stat[off + co_base + cl], sRed[tid]);
    }
  }
}

// =====================================================================
// Final deconv 128->3 with bias + tanh
// =====================================================================
__global__ void __launch_bounds__(128)
deconv2_kernel(const float* __restrict__ in, const float* __restrict__ w,
               const float* __restrict__ bias,
               const float* __restrict__ a_in, const float* __restrict__ c_in,
               float* __restrict__ out)
{
  constexpr int IC=128, IH=64, IW=64, TILE_M=16, CI=4, NG_N=8;
  constexpr int NT=128, ROWS=TILE_M+1, COLSP=IW+2;
  __shared__ float sIn[CI][ROWS][COLSP];
  __shared__ float sW[CI][4][4];

  const int tid = threadIdx.x;
  const int n_g = tid % NG_N;
  const int m_l = tid / NG_N;
  const int m0  = blockIdx.x * TILE_M;
  const int ry  = blockIdx.y >> 1, rx = blockIdx.y & 1;
  const int b   = blockIdx.z;
  const int n0  = n_g * 8;

  float acc[3][8];
  #pragma unroll
  for (int co=0;co<3;co++)
    #pragma unroll
    for (int u=0;u<8;u++) acc[co][u] = 0.f;

  for (int ci0 = 0; ci0 < IC; ci0 += CI) {
    for (int idx = tid; idx < CI*ROWS*COLSP; idx += NT) {
      int cc  = idx / (ROWS*COLSP);
      int rem = idx % (ROWS*COLSP);
      int r   = rem / COLSP, col = rem % COLSP;
      int gy  = m0 + ry - 1 + r;
      int gx  = rx - 1 + col;
      float v = 0.f;
      if (gy >= 0 && gy < IH && gx >= 0 && gx < IW)
        v = fmaxf(fmaf(a_in[ci0+cc], in[((b*IC + ci0+cc)*IH + gy)*IW + gx], c_in[ci0+cc]), 0.f);
      sIn[cc][r][col] = v;
    }
    if (tid < 48) {
      int cc = tid / 12, t4 = (tid / 3) % 4, co = tid % 3;
      int dd = t4 >> 1, ee = t4 & 1;
      sW[cc][t4][co] = w[((ci0+cc)*3 + co)*16 + (3-ry-2*dd)*4 + (3-rx-2*ee)];
    }
    __syncthreads();

    #pragma unroll
    for (int cc=0; cc<CI; cc++) {
      #pragma unroll
      for (int t4=0;t4<4;t4++) {
        const int dd = t4 >> 1, ee = t4 & 1;
        float w0 = sW[cc][t4][0], w1 = sW[cc][t4][1], w2 = sW[cc][t4][2];
        const float* rowp = &sIn[cc][m_l + dd][0];
        #pragma unroll
        for (int u=0;u<8;u++) {
          float iv = rowp[n0 + u + ee];
          acc[0][u] = fmaf(iv, w0, acc[0][u]);
          acc[1][u] = fmaf(iv, w1, acc[1][u]);
          acc[2][u] = fmaf(iv, w2, acc[2][u]);
        }
      }
    }
    __syncthreads();
  }

  const int oy = 2*(m0 + m_l) + ry;
  #pragma unroll
  for (int co=0;co<3;co++){
    float bb = bias[co];
    float* rp = &out[((b*3 + co)*128 + oy)*128 + rx];
    #pragma unroll
    for (int u=0;u<8;u++)
      rp[2*(n0+u)] = tanhf(acc[co][u] + bb);
  }
}

// =====================================================================
// stat[sum C | sq C] -> a = g*rsqrt(var+eps), c = be - mean*a
// =====================================================================
__global__ void finalize_kernel(const float* __restrict__ stat, const float* __restrict__ g,
                                const float* __restrict__ be,
                                float* __restrict__ a, float* __restrict__ cv,
                                int C, float invN)
{
  int c = threadIdx.x + blockIdx.x*blockDim.x;
  if (c >= C) return;
  float mean = stat[c] * invN;
  float var  = stat[C + c] * invN - mean*mean;
  float av = g[c] * rsqrtf(var + 1e-5f);
  a[c] = av;
  cv[c] = be[c] - mean * av;
}

__global__ void zero_kernel(float* s0, float* s1, float* s2, float* s3)
{
  int t = threadIdx.x;
  if (t < 128) s0[t] = 0.f;
  if (t < 256) s1[t] = 0.f;
  if (t < 512) s2[t] = 0.f;
  if (t < 256) s3[t] = 0.f;
}

// =====================================================================
// Pack Z_l (ch 64..95) and Z_g (ch 96..159) into Zbuf
// =====================================================================
__global__ void pack_kernel(const float* __restrict__ Zl, const float* __restrict__ Zg,
                            float* __restrict__ Zbuf)
{
  int idx = blockIdx.x * 256 + threadIdx.x;
  const int nl = 64*32*256;
  if (idx < nl) {
    int b = idx / (32*256); int r = idx % (32*256);
    Zbuf[(b*168 + 64)*256 + r] = Zl[idx];
  }
  const int ng = 64*64*256;
  if (idx < ng) {
    int b = idx / (64*256); int r = idx % (64*256);
    Zbuf[(b*168 + 96)*256 + r] = Zg[idx];
  }
}

// =====================================================================
// Wave latent: zg -> relu FC -> K1,K2 -> Z_p (ch 160..167)
// =====================================================================
__global__ void wave_kernel(const float* __restrict__ Zg, const float* __restrict__ phi,
                            const float* __restrict__ lW, const float* __restrict__ lb,
                            const float* __restrict__ l1W, const float* __restrict__ l1b,
                            const float* __restrict__ l2W, const float* __restrict__ l2b,
                            float* __restrict__ Zbuf)
{
  const int b = blockIdx.x;
  const int t = threadIdx.x;  // 64
  __shared__ float zg[64], x[64], K[16];
  zg[t] = Zg[(b*64 + t)*256];
  __syncthreads();
  float acc = lb[t];
  #pragma unroll 8
  for (int g = 0; g < 64; g++) acc = fmaf(zg[g], lW[t*64+g], acc);
  x[t] = fmaxf(acc, 0.f);
  __syncthreads();
  if (t < 16) {
    int p = t & 7;
    const float* W  = (t < 8) ? l1W : l2W;
    const float* bb = (t < 8) ? l1b : l2b;
    float k = bb[p];
    #pragma unroll 8
    for (int h = 0; h < 64; h++) k = fmaf(x[h], W[p*64+h], k);
    K[t] = k;
  }
  __syncthreads();
  for (int idx = t; idx < 8*256; idx += 64) {
    int p = idx >> 8; int ij = idx & 255; int i = ij >> 4; int j = ij & 15;
    float wv = K[p]*(float)i + K[p+8]*(float)j + phi[b*8+p]*TWO_PI_F;
    Zbuf[(b*168 + 160 + p)*256 + ij] = sinf(wv);
  }
}

// =====================================================================
extern "C" void kernel_launch(void* const* d_in, const int* in_sizes, int n_in,
                              void* d_out, int out_size)
{
  const float* Zl   = (const float*)d_in[0];
  const float* Zg   = (const float*)d_in[1];
  const float* imgs = (const float*)d_in[2];
  const float* phi  = (const float*)d_in[3];
  const float* lW   = (const float*)d_in[4];
  const float* lb   = (const float*)d_in[5];
  const float* l1W  = (const float*)d_in[6];
  const float* l1b  = (const float*)d_in[7];
  const float* l2W  = (const float*)d_in[8];
  const float* l2b  = (const float*)d_in[9];
  const float* cw0  = (const float*)d_in[10];
  const float* cg0  = (const float*)d_in[12];
  const float* cbe0 = (const float*)d_in[13];
  const float* cw1  = (const float*)d_in[14];
  const float* cg1  = (const float*)d_in[16];
  const float* cbe1 = (const float*)d_in[17];
  const float* cw2  = (const float*)d_in[18];
  const float* cb2  = (const float*)d_in[19];
  const float* gw0  = (const float*)d_in[20];
  const float* gg0  = (const float*)d_in[22];
  const float* gbe0 = (const float*)d_in[23];
  const float* gw1  = (const float*)d_in[24];
  const float* gg1  = (const float*)d_in[26];
  const float* gbe1 = (const float*)d_in[27];
  const float* gw2  = (const float*)d_in[28];
  const float* gb2  = (const float*)d_in[29];
  float* out = (float*)d_out;

  float *h0,*h1,*Zb,*g0,*g1;
  float *s0,*s1,*s2,*s3;
  float *a0,*c0,*a1,*c1,*a2,*c2,*a3,*c3;
  cudaGetSymbolAddress((void**)&h0, d_h0);
  cudaGetSymbolAddress((void**)&h1, d_h1);
  cudaGetSymbolAddress((void**)&Zb, d_Zbuf);
  cudaGetSymbolAddress((void**)&g0, d_g0);
  cudaGetSymbolAddress((void**)&g1, d_g1);
  cudaGetSymbolAddress((void**)&s0, d_stat0);
  cudaGetSymbolAddress((void**)&s1, d_stat1);
  cudaGetSymbolAddress((void**)&s2, d_stat2);
  cudaGetSymbolAddress((void**)&s3, d_stat3);
  cudaGetSymbolAddress((void**)&a0, d_a0); cudaGetSymbolAddress((void**)&c0, d_c0);
  cudaGetSymbolAddress((void**)&a1, d_a1); cudaGetSymbolAddress((void**)&c1, d_c1);
  cudaGetSymbolAddress((void**)&a2, d_a2); cudaGetSymbolAddress((void**)&c2, d_c2);
  cudaGetSymbolAddress((void**)&a3, d_a3); cudaGetSymbolAddress((void**)&c3, d_c3);

  zero_kernel<<<1,512>>>(s0, s1, s2, s3);
  pack_kernel<<<4096,256>>>(Zl, Zg, Zb);
  wave_kernel<<<64,64>>>(Zg, phi, lW, lb, l1W, l1b, l2W, l2b, Zb);

  // encoder (stats fused)
  conv_s2_kernel<3,64,128,128,64,64, 64, 4,64,3,8,8, false,false,false,true>
      <<<dim3(16,1,64),256>>>(imgs, cw0, nullptr, nullptr, nullptr, h0, s0);
  finalize_kernel<<<1,64>>>(s0, cg0, cbe0, a0, c0, 64, 1.f/(64.f*4096.f));
  conv_s2_kernel<64,128,64,64,32,32, 128, 8,64,4,4,8, true,false,false,true>
      <<<dim3(4,2,64),256>>>(h0, cw1, nullptr, a0, c0, h1, s1);
  finalize_kernel<<<1,128>>>(s1, cg1, cbe1, a1, c1, 128, 1.f/(64.f*1024.f));
  conv_s2_kernel<128,64,32,32,16,16, 168, 8,64,4,2,16, true,true,true,false>
      <<<dim3(2,1,64),256>>>(h1, cw2, cb2, a1, c1, Zb, nullptr);

  // generator (stats fused)
  deconv_kernel<168,256,16,16, 256, 8,128,8,2,16, false,true>
      <<<dim3(4,4,64),256>>>(Zb, gw0, nullptr, nullptr, g0, s2);
  finalize_kernel<<<1,256>>>(s2, gg0, gbe0, a2, c2, 256, 1.f/(64.f*1024.f));
  deconv_kernel<256,128,32,32, 128, 8,128,8,4,16, true,true>
      <<<dim3(4,4,64),512>>>(g0, gw1, a2, c2, g1, s3);
  finalize_kernel<<<1,128>>>(s3, gg1, gbe1, a3, c3, 128, 1.f/(64.f*4096.f));
  deconv2_kernel<<<dim3(4,4,64),128>>>(g1, gw2, gb2, a3, c3, out);
}